// round 4
// baseline (speedup 1.0000x reference)
#include <cuda_runtime.h>
#include <cuda_fp16.h>
#include <math.h>

#define Bn 4
#define Hn 1080
#define Wn 1920
#define HWn (Hn * Wn)   // 2073600

// ---------------- scratch (no runtime allocation allowed) ----------------
__device__ __align__(16) __half g_diff[Bn * HWn];   // fp16: continuous channel
__device__ __align__(16) __half g_cd  [Bn * HWn];   // fp16: continuous channel
__device__ __align__(16) float  g_gr  [Bn * HWn];   // fp32: threshold-sensitive
__device__ __align__(16) float  g_gt  [Bn * HWn];
__device__ int   g_maxd_i;
__device__ int   g_maxcd_i;
__device__ float g_sum[Bn];
__device__ float g_invd, g_invcd;

static __forceinline__ __device__ unsigned h2u(__half2 h) {
    return *reinterpret_cast<unsigned*>(&h);
}

// ---------------- K0: zero reduction scalars (graph replays!) ------------
__global__ void k0_init() {
    int t = threadIdx.x;
    if (t == 0) g_maxd_i = 0;
    if (t == 1) g_maxcd_i = 0;
    if (t >= 2 && t < 2 + Bn) g_sum[t - 2] = 0.f;
}

// ---------------- K1: pointwise diff/gray + global reductions ------------
__global__ __launch_bounds__(256) void k1_point(const float* __restrict__ ref,
                                                const float* __restrict__ tgt) {
    const int b = blockIdx.y;
    const int v = blockIdx.x * blockDim.x + threadIdx.x;  // float4 index
    float lmaxd = 0.f, lmaxcd = 0.f, lsum = 0.f;

    if (v < HWn / 4) {
        const float4* R0 = (const float4*)(ref + (size_t)(b * 3 + 0) * HWn);
        const float4* R1 = (const float4*)(ref + (size_t)(b * 3 + 1) * HWn);
        const float4* R2 = (const float4*)(ref + (size_t)(b * 3 + 2) * HWn);
        const float4* T0 = (const float4*)(tgt + (size_t)(b * 3 + 0) * HWn);
        const float4* T1 = (const float4*)(tgt + (size_t)(b * 3 + 1) * HWn);
        const float4* T2 = (const float4*)(tgt + (size_t)(b * 3 + 2) * HWn);

        float4 r0 = R0[v], r1 = R1[v], r2 = R2[v];
        float4 t0 = T0[v], t1 = T1[v], t2 = T2[v];
        float4 D, C, GR, GT;

#define LANE(c)                                                               \
        {                                                                     \
            float d0 = r0.c - t0.c, d1 = r1.c - t1.c, d2 = r2.c - t2.c;       \
            float df = sqrtf(d0 * d0 + d1 * d1 + d2 * d2);                    \
            float cd = (fabsf(d0) + fabsf(d1) + fabsf(d2)) * (1.f / 3.f);     \
            D.c = df; C.c = cd;                                               \
            GR.c = 0.299f * r0.c + 0.587f * r1.c + 0.114f * r2.c;             \
            GT.c = 0.299f * t0.c + 0.587f * t1.c + 0.114f * t2.c;             \
            lmaxd = fmaxf(lmaxd, df); lmaxcd = fmaxf(lmaxcd, cd);             \
            lsum += df;                                                       \
        }
        LANE(x) LANE(y) LANE(z) LANE(w)
#undef LANE

        uint2 dv, cv;
        dv.x = h2u(__floats2half2_rn(D.x, D.y));
        dv.y = h2u(__floats2half2_rn(D.z, D.w));
        cv.x = h2u(__floats2half2_rn(C.x, C.y));
        cv.y = h2u(__floats2half2_rn(C.z, C.w));
        ((uint2*)(g_diff + (size_t)b * HWn))[v] = dv;
        ((uint2*)(g_cd   + (size_t)b * HWn))[v] = cv;
        ((float4*)(g_gr  + (size_t)b * HWn))[v] = GR;
        ((float4*)(g_gt  + (size_t)b * HWn))[v] = GT;
    }

    #pragma unroll
    for (int o = 16; o > 0; o >>= 1) {
        lmaxd  = fmaxf(lmaxd,  __shfl_xor_sync(0xffffffffu, lmaxd,  o));
        lmaxcd = fmaxf(lmaxcd, __shfl_xor_sync(0xffffffffu, lmaxcd, o));
        lsum  +=               __shfl_xor_sync(0xffffffffu, lsum,   o);
    }
    __shared__ float smx[8], smc[8], sms[8];
    const int lane = threadIdx.x & 31, wid = threadIdx.x >> 5;
    if (lane == 0) { smx[wid] = lmaxd; smc[wid] = lmaxcd; sms[wid] = lsum; }
    __syncthreads();
    if (threadIdx.x == 0) {
        float mx = smx[0], mc = smc[0], s = sms[0];
        #pragma unroll
        for (int i = 1; i < 8; i++) {
            mx = fmaxf(mx, smx[i]); mc = fmaxf(mc, smc[i]); s += sms[i];
        }
        atomicMax(&g_maxd_i,  __float_as_int(mx));
        atomicMax(&g_maxcd_i, __float_as_int(mc));
        atomicAdd(&g_sum[b], s);
    }
}

// ---------------- K2: score + inverse normalizers ------------------------
__global__ void k2_score(float* __restrict__ out) {
    const int t = threadIdx.x;
    const float invd  = 1.f / (__int_as_float(g_maxd_i)  + 1e-12f);
    const float invcd = 1.f / (__int_as_float(g_maxcd_i) + 1e-12f);
    if (t == 0) { g_invd = invd; g_invcd = invcd; }
    if (t < Bn) {
        float m = g_sum[t] * (1.f / (float)HWn) * invd;
        out[t] = fminf(fmaxf(1.f - m, 0.f), 1.f);
    }
}

// ---------------- K3: fused stencils + diagnostic write -------------------
// 32x32 output tile, 256 threads (32x8). smem ~28.3KB, 7 blocks/SM target.
// Gray tiles are 40 cols wide starting at x0-4 (float4-aligned loads);
// col i of sgr/sgt corresponds to global x = x0 - 4 + i.
__global__ __launch_bounds__(256, 7) void k3_stencil(float* __restrict__ diag) {
    const int b  = blockIdx.z;
    const int x0 = blockIdx.x * 32;
    const int y0 = blockIdx.y * 32;

    // region1: sgr during stages 1-2, hmax during stages 3-4
    __shared__ __align__(16) float region1[38 * 41];
    float (*sgr)[41]  = reinterpret_cast<float(*)[41]>(region1);
    float (*hmax)[33] = reinterpret_cast<float(*)[33]>(region1);  // 36*33 <= 38*41
    __shared__ __align__(16) float sgt[38][41];
    __shared__ __align__(16) float2 hrt[38][33];   // (hsum_ref, hsum_tgt)
    __shared__ float sedge[36][37];
    __shared__ float sax[32][5];                   // |gx| at cols {0,8,16,24}
    __shared__ float say[4][33];                   // |gy| at rows {0,8,16,24}

    const int tid = threadIdx.y * 32 + threadIdx.x;
    const float* grb = g_gr + (size_t)b * HWn;
    const float* gtb = g_gt + (size_t)b * HWn;

    // ---- stage 1: vectorized load of gray tiles (zero-padded) ----
    // 38 rows x 10 float4 = 380 vector slots, both arrays per slot.
    for (int p = tid; p < 380; p += 256) {
        int j = p / 10, v = p - j * 10;
        int y = y0 - 3 + j;
        int x = x0 - 4 + v * 4;
        float4 A = make_float4(0.f, 0.f, 0.f, 0.f);
        float4 C = A;
        if (y >= 0 && y < Hn) {
            const size_t rb = (size_t)y * Wn;
            if (x >= 0 && x + 3 < Wn) {
                A = *(const float4*)(grb + rb + x);
                C = *(const float4*)(gtb + rb + x);
            } else {
                if (x + 0 >= 0 && x + 0 < Wn) { A.x = grb[rb + x];     C.x = gtb[rb + x]; }
                if (x + 1 >= 0 && x + 1 < Wn) { A.y = grb[rb + x + 1]; C.y = gtb[rb + x + 1]; }
                if (x + 2 >= 0 && x + 2 < Wn) { A.z = grb[rb + x + 2]; C.z = gtb[rb + x + 2]; }
                if (x + 3 >= 0 && x + 3 < Wn) { A.w = grb[rb + x + 3]; C.w = gtb[rb + x + 3]; }
            }
        }
        const int c0 = v * 4;
        sgr[j][c0] = A.x; sgr[j][c0 + 1] = A.y; sgr[j][c0 + 2] = A.z; sgr[j][c0 + 3] = A.w;
        sgt[j][c0] = C.x; sgt[j][c0 + 1] = C.y; sgt[j][c0 + 2] = C.z; sgt[j][c0 + 3] = C.w;
    }
    __syncthreads();

    // ---- stage 2a: horizontal 7-sums, groups of 8, single pass (152 thr) ----
    // output col o (0..31): sum of sgr[j][o+1 .. o+7]
    for (int p = tid; p < 38 * 4; p += 256) {
        int j = p >> 2, g = p & 3;
        int o0 = g * 8;
        float a[14], c[14];
        #pragma unroll
        for (int k = 0; k < 14; k++) { a[k] = sgr[j][o0 + 1 + k]; c[k] = sgt[j][o0 + 1 + k]; }
        float sr = a[0] + a[1] + a[2] + a[3] + a[4] + a[5] + a[6];
        float st = c[0] + c[1] + c[2] + c[3] + c[4] + c[5] + c[6];
        hrt[j][o0] = make_float2(sr, st);
        #pragma unroll
        for (int q = 1; q < 8; q++) {
            sr += a[q + 6] - a[q - 1];
            st += c[q + 6] - c[q - 1];
            hrt[j][o0 + q] = make_float2(sr, st);
        }
    }

    // ---- stage 2b: Sobel + edge map, groups of 6, single pass (216 thr) ----
    // edge (j,i) <-> global (y0-2+j, x0-2+i); center sgt col = i+2
    for (int p = tid; p < 36 * 6; p += 256) {
        int j = p / 6, g = p - j * 6;
        int i0 = g * 6;
        float r0[8], r1[8], r2[8];
        #pragma unroll
        for (int k = 0; k < 8; k++) {
            r0[k] = sgt[j][i0 + 1 + k];
            r1[k] = sgt[j + 1][i0 + 1 + k];
            r2[k] = sgt[j + 2][i0 + 1 + k];
        }
        #pragma unroll
        for (int q = 0; q < 6; q++) {
            float gxv = (r0[q+2] - r0[q]) + 2.f * (r1[q+2] - r1[q]) + (r2[q+2] - r2[q]);
            float gyv = (r2[q] - r0[q]) + 2.f * (r2[q+1] - r0[q+1]) + (r2[q+2] - r0[q+2]);
            int i  = i0 + q;
            int ye = y0 - 2 + j, xe = x0 - 2 + i;
            bool in = (ye >= 0) & (ye < Hn) & (xe >= 0) & (xe < Wn);
            float e = (in && (sqrtf(gxv * gxv + gyv * gyv) > 0.15f)) ? 1.f : 0.f;
            sedge[j][i] = e;
            int yl = j - 2, xl = i - 2;
            if (((xl & 7) == 0) & (xl >= 0) & (xl < 32) & (yl >= 0) & (yl < 32))
                sax[yl][xl >> 3] = fabsf(gxv);
            if (((yl & 7) == 0) & (yl >= 0) & (yl < 32) & (xl >= 0) & (xl < 32))
                say[yl >> 3][xl] = fabsf(gyv);
        }
    }
    __syncthreads();   // sgr dead; region1 becomes hmax

    // ---- stage 3: horizontal 5-max, groups of 8, single pass (144 thr) ----
    // hmax[j][o] = max sedge[j][o .. o+4]
    for (int p = tid; p < 36 * 4; p += 256) {
        int j = p >> 2, g = p & 3;
        int xg = g * 8;
        float v[12];
        #pragma unroll
        for (int k = 0; k < 12; k++) v[k] = sedge[j][xg + k];
        float t2[10];
        #pragma unroll
        for (int k = 0; k < 10; k++) t2[k] = fmaxf(v[k], v[k + 1]);
        #pragma unroll
        for (int q = 0; q < 8; q++)
            hmax[j][xg + q] = fmaxf(fmaxf(t2[q], t2[q + 2]), v[q + 4]);
    }
    __syncthreads();

    // ---- stage 4: per-pixel outputs, 4 consecutive rows per thread ----
    const float invd  = g_invd;
    const float invcd = g_invcd;
    const __half* diffp = g_diff + (size_t)b * HWn;
    const __half* cdp   = g_cd   + (size_t)b * HWn;
    float* o_an = diag + ((size_t)b * 5 + 0) * HWn;
    float* o_cm = diag + ((size_t)b * 5 + 1) * HWn;
    float* o_ss = diag + ((size_t)b * 5 + 2) * HWn;
    float* o_bl = diag + ((size_t)b * 5 + 3) * HWn;
    float* o_ri = diag + ((size_t)b * 5 + 4) * HWn;

    const int x  = threadIdx.x;
    const int gx = x0 + x;
    const int yb = threadIdx.y * 4;

    float2 vrt[10];
    #pragma unroll
    for (int k = 0; k < 10; k++) vrt[k] = hrt[yb + k][x];
    float mur[4], mut[4];
    {
        float sr = vrt[0].x + vrt[1].x + vrt[2].x + vrt[3].x + vrt[4].x + vrt[5].x + vrt[6].x;
        float st = vrt[0].y + vrt[1].y + vrt[2].y + vrt[3].y + vrt[4].y + vrt[5].y + vrt[6].y;
        mur[0] = sr; mut[0] = st;
        sr += vrt[7].x - vrt[0].x; st += vrt[7].y - vrt[0].y; mur[1] = sr; mut[1] = st;
        sr += vrt[8].x - vrt[1].x; st += vrt[8].y - vrt[1].y; mur[2] = sr; mut[2] = st;
        sr += vrt[9].x - vrt[2].x; st += vrt[9].y - vrt[2].y; mur[3] = sr; mut[3] = st;
    }

    float hm[8];
    #pragma unroll
    for (int k = 0; k < 8; k++) hm[k] = hmax[yb + k][x];
    float dil[4];
    {
        float m34 = fmaxf(hm[3], hm[4]);
        float m234 = fmaxf(hm[2], m34);
        float m345 = fmaxf(m34, hm[5]);
        dil[0] = fmaxf(fmaxf(hm[0], hm[1]), m234);
        dil[1] = fmaxf(hm[1], fmaxf(m234, hm[5]));
        dil[2] = fmaxf(hm[2], fmaxf(m345, hm[6]));
        dil[3] = fmaxf(fmaxf(m345, hm[6]), hm[7]);
    }

    float ev[4];
    #pragma unroll
    for (int r = 0; r < 4; r++) ev[r] = sedge[yb + r + 2][x + 2];

    const bool colblk = ((gx & 7) == 0);
    float axv[4];
    #pragma unroll
    for (int r = 0; r < 4; r++) axv[r] = colblk ? sax[yb + r][x >> 3] : 0.f;

    #pragma unroll
    for (int r = 0; r < 4; r++) {
        const int y  = yb + r;
        const int gy = y0 + y;
        if (gy >= Hn) continue;

        float mu_r = mur[r] * (1.f / 49.f), mu_t = mut[r] * (1.f / 49.f);
        float ssim = (2.f * mu_r * mu_t + 1e-4f) / (mu_r * mu_r + mu_t * mu_t + 1e-4f);

        float blk = axv[r];
        if ((y & 7) == 0) blk = fmaxf(blk, say[y >> 3][x]);
        blk = (blk > 0.05f) ? 1.f : 0.f;

        const int idx = gy * Wn + gx;
        float an   = __half2float(__ldg(diffp + idx)) * invd;
        float cm   = __half2float(__ldg(cdp   + idx)) * invcd;
        float ring = fmaxf(dil[r] - ev[r], 0.f) * an;

        o_an[idx] = an;
        o_cm[idx] = cm;
        o_ss[idx] = ssim;
        o_bl[idx] = blk;
        o_ri[idx] = ring;
    }
}

// ---------------- launch ---------------------------------------------------
extern "C" void kernel_launch(void* const* d_in, const int* in_sizes, int n_in,
                              void* d_out, int out_size) {
    const float* ref = (const float*)d_in[0];
    const float* tgt = (const float*)d_in[1];
    float* out = (float*)d_out;

    k0_init<<<1, 32>>>();

    dim3 g1((HWn / 4 + 255) / 256, Bn);
    k1_point<<<g1, 256>>>(ref, tgt);

    k2_score<<<1, 32>>>(out);

    dim3 g3((Wn + 31) / 32, (Hn + 31) / 32, Bn);
    dim3 b3(32, 8);
    k3_stencil<<<g3, b3>>>(out + Bn);
}

// round 5
// speedup vs baseline: 1.0340x; 1.0340x over previous
#include <cuda_runtime.h>
#include <cuda_fp16.h>
#include <math.h>

#define Bn 4
#define Hn 1080
#define Wn 1920
#define HWn (Hn * Wn)   // 2073600

// ---------------- scratch (no runtime allocation allowed) ----------------
__device__ __align__(16) __half g_diff[Bn * HWn];   // fp16 sqrt-diff
__device__ __align__(16) __half g_cd  [Bn * HWn];   // fp16 color diff
__device__ __align__(16) float  g_gt  [Bn * HWn];   // tgt gray (fp32, Sobel)
__device__ __align__(16) float2 g_hrt [Bn * HWn];   // (hsum7_ref, hsum7_tgt)
__device__ int   g_maxd_i;
__device__ int   g_maxcd_i;
__device__ float g_sum[Bn];
__device__ float g_invd, g_invcd;

static __forceinline__ __device__ unsigned h2u(__half2 h) {
    return *reinterpret_cast<unsigned*>(&h);
}

// ---------------- K0: zero reduction scalars (graph replays!) ------------
__global__ void k0_init() {
    int t = threadIdx.x;
    if (t == 0) g_maxd_i = 0;
    if (t == 1) g_maxcd_i = 0;
    if (t >= 2 && t < 2 + Bn) g_sum[t - 2] = 0.f;
}

// ---------------- K1: one row per block; pointwise + horizontal 7-sums ---
// 480 threads, each owns one float4 (4 px) of a 1920-px row.
__global__ __launch_bounds__(480) void k1_point(const float* __restrict__ ref,
                                                const float* __restrict__ tgt) {
    const int y = blockIdx.x;
    const int b = blockIdx.y;
    const int t = threadIdx.x;           // 0..479

    __shared__ __align__(16) float srow_r[1928];   // 4 zero pad each side
    __shared__ __align__(16) float srow_t[1928];
    __shared__ float smx[15], smc[15], sms[15];

    if (t < 4) {
        srow_r[t] = 0.f; srow_t[t] = 0.f;
        srow_r[1924 + t] = 0.f; srow_t[1924 + t] = 0.f;
    }

    const size_t rowpx = (size_t)y * Wn + 4 * t;
    const int v = (int)(rowpx >> 2);     // float4 index within plane

    const float4 r0 = ((const float4*)(ref + (size_t)(b * 3 + 0) * HWn))[v];
    const float4 r1 = ((const float4*)(ref + (size_t)(b * 3 + 1) * HWn))[v];
    const float4 r2 = ((const float4*)(ref + (size_t)(b * 3 + 2) * HWn))[v];
    const float4 t0 = ((const float4*)(tgt + (size_t)(b * 3 + 0) * HWn))[v];
    const float4 t1 = ((const float4*)(tgt + (size_t)(b * 3 + 1) * HWn))[v];
    const float4 t2 = ((const float4*)(tgt + (size_t)(b * 3 + 2) * HWn))[v];

    float4 D, C, GR, GT;
    float lmaxd = 0.f, lmaxcd = 0.f, lsum = 0.f;

#define LANE(c)                                                               \
    {                                                                         \
        float d0 = r0.c - t0.c, d1 = r1.c - t1.c, d2 = r2.c - t2.c;           \
        float df = sqrtf(d0 * d0 + d1 * d1 + d2 * d2);                        \
        float cd = (fabsf(d0) + fabsf(d1) + fabsf(d2)) * (1.f / 3.f);         \
        D.c = df; C.c = cd;                                                   \
        GR.c = 0.299f * r0.c + 0.587f * r1.c + 0.114f * r2.c;                 \
        GT.c = 0.299f * t0.c + 0.587f * t1.c + 0.114f * t2.c;                 \
        lmaxd = fmaxf(lmaxd, df); lmaxcd = fmaxf(lmaxcd, cd);                 \
        lsum += df;                                                           \
    }
    LANE(x) LANE(y) LANE(z) LANE(w)
#undef LANE

    // stores: fp16 diff/cd, fp32 gt gray
    uint2 dv, cv;
    dv.x = h2u(__floats2half2_rn(D.x, D.y));
    dv.y = h2u(__floats2half2_rn(D.z, D.w));
    cv.x = h2u(__floats2half2_rn(C.x, C.y));
    cv.y = h2u(__floats2half2_rn(C.z, C.w));
    ((uint2*)(g_diff + (size_t)b * HWn))[v] = dv;
    ((uint2*)(g_cd   + (size_t)b * HWn))[v] = cv;
    ((float4*)(g_gt  + (size_t)b * HWn))[v] = GT;

    // stage gray row for horizontal sums
    *(float4*)&srow_r[4 + 4 * t] = GR;
    *(float4*)&srow_t[4 + 4 * t] = GT;

    // block reduction
    #pragma unroll
    for (int o = 16; o > 0; o >>= 1) {
        lmaxd  = fmaxf(lmaxd,  __shfl_xor_sync(0xffffffffu, lmaxd,  o));
        lmaxcd = fmaxf(lmaxcd, __shfl_xor_sync(0xffffffffu, lmaxcd, o));
        lsum  +=               __shfl_xor_sync(0xffffffffu, lsum,   o);
    }
    const int lane = t & 31, wid = t >> 5;
    if (lane == 0) { smx[wid] = lmaxd; smc[wid] = lmaxcd; sms[wid] = lsum; }
    __syncthreads();
    if (t == 0) {
        float mx = smx[0], mc = smc[0], s = sms[0];
        #pragma unroll
        for (int i = 1; i < 15; i++) {
            mx = fmaxf(mx, smx[i]); mc = fmaxf(mc, smc[i]); s += sms[i];
        }
        atomicMax(&g_maxd_i,  __float_as_int(mx));
        atomicMax(&g_maxcd_i, __float_as_int(mc));
        atomicAdd(&g_sum[b], s);
    }

    // horizontal 7-sums for cols 4t..4t+3 (window +-3, zero padded)
    // a[k] = col 4t-4+k, k=0..11
    const float* ar = srow_r + 4 * t;
    const float* at = srow_t + 4 * t;
    float4 A0 = *(const float4*)(ar), A1 = *(const float4*)(ar + 4), A2 = *(const float4*)(ar + 8);
    float4 B0 = *(const float4*)(at), B1 = *(const float4*)(at + 4), B2 = *(const float4*)(at + 8);
    float a[12] = {A0.x,A0.y,A0.z,A0.w, A1.x,A1.y,A1.z,A1.w, A2.x,A2.y,A2.z,A2.w};
    float c[12] = {B0.x,B0.y,B0.z,B0.w, B1.x,B1.y,B1.z,B1.w, B2.x,B2.y,B2.z,B2.w};

    float hr0 = a[1]+a[2]+a[3]+a[4]+a[5]+a[6]+a[7];
    float ht0 = c[1]+c[2]+c[3]+c[4]+c[5]+c[6]+c[7];
    float hr1 = hr0 + a[8] - a[1], ht1 = ht0 + c[8] - c[1];
    float hr2 = hr1 + a[9] - a[2], ht2 = ht1 + c[9] - c[2];
    float hr3 = hr2 + a[10] - a[3], ht3 = ht2 + c[10] - c[3];

    float4* hp = (float4*)(g_hrt + (size_t)b * HWn);
    hp[2 * v + 0] = make_float4(hr0, ht0, hr1, ht1);
    hp[2 * v + 1] = make_float4(hr2, ht2, hr3, ht3);
}

// ---------------- K2: score + inverse normalizers ------------------------
__global__ void k2_score(float* __restrict__ out) {
    const int t = threadIdx.x;
    const float invd  = 1.f / (__int_as_float(g_maxd_i)  + 1e-12f);
    const float invcd = 1.f / (__int_as_float(g_maxcd_i) + 1e-12f);
    if (t == 0) { g_invd = invd; g_invcd = invcd; }
    if (t < Bn) {
        float m = g_sum[t] * (1.f / (float)HWn) * invd;
        out[t] = fminf(fmaxf(1.f - m, 0.f), 1.f);
    }
}

// ---------------- K3: fused stencils + diagnostic write -------------------
// 32x32 tile, 256 threads (32x8). smem ~23KB -> 8 blocks/SM.
__global__ __launch_bounds__(256, 8) void k3_stencil(float* __restrict__ diag) {
    const int b  = blockIdx.z;
    const int x0 = blockIdx.x * 32;
    const int y0 = blockIdx.y * 32;

    // region1: sgt (38x41) during stages 1-2, hmax (36x33) during 3-4
    __shared__ __align__(16) float region1[38 * 41];
    float (*sgt)[41]  = reinterpret_cast<float(*)[41]>(region1);
    float (*hmax)[33] = reinterpret_cast<float(*)[33]>(region1);
    __shared__ __align__(16) float2 shrt[38][34];  // even stride for float4 ST
    __shared__ float sedge[36][37];
    __shared__ float sax[32][5];                   // |gx| at cols {0,8,16,24}
    __shared__ float say[4][33];                   // |gy| at rows {0,8,16,24}

    const int tid = threadIdx.y * 32 + threadIdx.x;
    const int x   = threadIdx.x;
    const int gx  = x0 + x;
    const int yb  = threadIdx.y * 4;

    // ---- prefetch diff/cd for this thread's 4 pixels (overlaps stage 1) ----
    const __half* diffp = g_diff + (size_t)b * HWn;
    const __half* cdp   = g_cd   + (size_t)b * HWn;
    __half pd[4], pc[4];
    #pragma unroll
    for (int r = 0; r < 4; r++) {
        int gy = y0 + yb + r;
        int idx = (gy < Hn) ? gy * Wn + gx : 0;
        pd[r] = __ldg(diffp + idx);
        pc[r] = __ldg(cdp + idx);
    }

    const float*  gtb = g_gt  + (size_t)b * HWn;
    const float2* hqb = g_hrt + (size_t)b * HWn;

    // ---- stage 1a: load hrt tile (38 rows x 32 cols, vertical halo only) ----
    for (int p = tid; p < 38 * 16; p += 256) {
        int j = p >> 4, s = p & 15;
        int y = y0 - 3 + j;
        float4 V = make_float4(0.f, 0.f, 0.f, 0.f);
        if (y >= 0 && y < Hn)
            V = ((const float4*)(hqb + (size_t)y * Wn + x0))[s];
        *(float4*)&shrt[j][2 * s] = V;
    }
    // ---- stage 1b: load gt gray tile (38 x 40 from x0-4, zero-pad) ----
    for (int p = tid; p < 380; p += 256) {
        int j = p / 10, vv = p - j * 10;
        int y = y0 - 3 + j;
        int xg = x0 - 4 + vv * 4;
        float4 C4 = make_float4(0.f, 0.f, 0.f, 0.f);
        if (y >= 0 && y < Hn) {
            const size_t rb = (size_t)y * Wn;
            if (xg >= 0 && xg + 3 < Wn) {
                C4 = *(const float4*)(gtb + rb + xg);
            } else {
                if (xg + 0 >= 0 && xg + 0 < Wn) C4.x = gtb[rb + xg];
                if (xg + 1 >= 0 && xg + 1 < Wn) C4.y = gtb[rb + xg + 1];
                if (xg + 2 >= 0 && xg + 2 < Wn) C4.z = gtb[rb + xg + 2];
                if (xg + 3 >= 0 && xg + 3 < Wn) C4.w = gtb[rb + xg + 3];
            }
        }
        const int c0 = vv * 4;
        sgt[j][c0] = C4.x; sgt[j][c0 + 1] = C4.y; sgt[j][c0 + 2] = C4.z; sgt[j][c0 + 3] = C4.w;
    }
    __syncthreads();

    // ---- stage 2: Sobel + edge map over halo-2 region, groups of 6 ----
    for (int p = tid; p < 36 * 6; p += 256) {
        int j = p / 6, g = p - j * 6;
        int i0 = g * 6;
        float r0[8], r1[8], r2[8];
        #pragma unroll
        for (int k = 0; k < 8; k++) {
            r0[k] = sgt[j][i0 + 1 + k];
            r1[k] = sgt[j + 1][i0 + 1 + k];
            r2[k] = sgt[j + 2][i0 + 1 + k];
        }
        #pragma unroll
        for (int q = 0; q < 6; q++) {
            float gxv = (r0[q+2] - r0[q]) + 2.f * (r1[q+2] - r1[q]) + (r2[q+2] - r2[q]);
            float gyv = (r2[q] - r0[q]) + 2.f * (r2[q+1] - r0[q+1]) + (r2[q+2] - r0[q+2]);
            int i  = i0 + q;
            int ye = y0 - 2 + j, xe = x0 - 2 + i;
            bool in = (ye >= 0) & (ye < Hn) & (xe >= 0) & (xe < Wn);
            float e = (in && (sqrtf(gxv * gxv + gyv * gyv) > 0.15f)) ? 1.f : 0.f;
            sedge[j][i] = e;
            int yl = j - 2, xl = i - 2;
            if (((xl & 7) == 0) & (xl >= 0) & (xl < 32) & (yl >= 0) & (yl < 32))
                sax[yl][xl >> 3] = fabsf(gxv);
            if (((yl & 7) == 0) & (yl >= 0) & (yl < 32) & (xl >= 0) & (xl < 32))
                say[yl >> 3][xl] = fabsf(gyv);
        }
    }
    __syncthreads();   // sgt dead; region1 becomes hmax

    // ---- stage 3: horizontal 5-max of edges, groups of 8 ----
    for (int p = tid; p < 36 * 4; p += 256) {
        int j = p >> 2, g = p & 3;
        int xg = g * 8;
        float v[12];
        #pragma unroll
        for (int k = 0; k < 12; k++) v[k] = sedge[j][xg + k];
        float t2[10];
        #pragma unroll
        for (int k = 0; k < 10; k++) t2[k] = fmaxf(v[k], v[k + 1]);
        #pragma unroll
        for (int q = 0; q < 8; q++)
            hmax[j][xg + q] = fmaxf(fmaxf(t2[q], t2[q + 2]), v[q + 4]);
    }
    __syncthreads();

    // ---- stage 4: per-pixel outputs, 4 consecutive rows per thread ----
    const float invd  = g_invd;
    const float invcd = g_invcd;
    float* o_an = diag + ((size_t)b * 5 + 0) * HWn;
    float* o_cm = diag + ((size_t)b * 5 + 1) * HWn;
    float* o_ss = diag + ((size_t)b * 5 + 2) * HWn;
    float* o_bl = diag + ((size_t)b * 5 + 3) * HWn;
    float* o_ri = diag + ((size_t)b * 5 + 4) * HWn;

    float2 vrt[10];
    #pragma unroll
    for (int k = 0; k < 10; k++) vrt[k] = shrt[yb + k][x];
    float mur[4], mut[4];
    {
        float sr = vrt[0].x + vrt[1].x + vrt[2].x + vrt[3].x + vrt[4].x + vrt[5].x + vrt[6].x;
        float st = vrt[0].y + vrt[1].y + vrt[2].y + vrt[3].y + vrt[4].y + vrt[5].y + vrt[6].y;
        mur[0] = sr; mut[0] = st;
        sr += vrt[7].x - vrt[0].x; st += vrt[7].y - vrt[0].y; mur[1] = sr; mut[1] = st;
        sr += vrt[8].x - vrt[1].x; st += vrt[8].y - vrt[1].y; mur[2] = sr; mut[2] = st;
        sr += vrt[9].x - vrt[2].x; st += vrt[9].y - vrt[2].y; mur[3] = sr; mut[3] = st;
    }

    float hm[8];
    #pragma unroll
    for (int k = 0; k < 8; k++) hm[k] = hmax[yb + k][x];
    float dil[4];
    {
        float m34 = fmaxf(hm[3], hm[4]);
        float m234 = fmaxf(hm[2], m34);
        float m345 = fmaxf(m34, hm[5]);
        dil[0] = fmaxf(fmaxf(hm[0], hm[1]), m234);
        dil[1] = fmaxf(hm[1], fmaxf(m234, hm[5]));
        dil[2] = fmaxf(hm[2], fmaxf(m345, hm[6]));
        dil[3] = fmaxf(fmaxf(m345, hm[6]), hm[7]);
    }

    float ev[4];
    #pragma unroll
    for (int r = 0; r < 4; r++) ev[r] = sedge[yb + r + 2][x + 2];

    const bool colblk = ((gx & 7) == 0);
    float axv[4];
    #pragma unroll
    for (int r = 0; r < 4; r++) axv[r] = colblk ? sax[yb + r][x >> 3] : 0.f;

    #pragma unroll
    for (int r = 0; r < 4; r++) {
        const int y  = yb + r;
        const int gy = y0 + y;
        if (gy >= Hn) continue;

        float mu_r = mur[r] * (1.f / 49.f), mu_t = mut[r] * (1.f / 49.f);
        float ssim = (2.f * mu_r * mu_t + 1e-4f) / (mu_r * mu_r + mu_t * mu_t + 1e-4f);

        float blk = axv[r];
        if ((y & 7) == 0) blk = fmaxf(blk, say[y >> 3][x]);
        blk = (blk > 0.05f) ? 1.f : 0.f;

        const int idx = gy * Wn + gx;
        float an   = __half2float(pd[r]) * invd;
        float cm   = __half2float(pc[r]) * invcd;
        float ring = fmaxf(dil[r] - ev[r], 0.f) * an;

        o_an[idx] = an;
        o_cm[idx] = cm;
        o_ss[idx] = ssim;
        o_bl[idx] = blk;
        o_ri[idx] = ring;
    }
}

// ---------------- launch ---------------------------------------------------
extern "C" void kernel_launch(void* const* d_in, const int* in_sizes, int n_in,
                              void* d_out, int out_size) {
    const float* ref = (const float*)d_in[0];
    const float* tgt = (const float*)d_in[1];
    float* out = (float*)d_out;

    k0_init<<<1, 32>>>();

    dim3 g1(Hn, Bn);
    k1_point<<<g1, 480>>>(ref, tgt);

    k2_score<<<1, 32>>>(out);

    dim3 g3((Wn + 31) / 32, (Hn + 31) / 32, Bn);
    dim3 b3(32, 8);
    k3_stencil<<<g3, b3>>>(out + Bn);
}

// round 6
// speedup vs baseline: 1.1306x; 1.0934x over previous
#include <cuda_runtime.h>
#include <cuda_fp16.h>
#include <math.h>

#define Bn 4
#define Hn 1080
#define Wn 1920
#define HWn (Hn * Wn)   // 2073600

// ---------------- scratch (no runtime allocation allowed) ----------------
__device__ __align__(16) __half2 g_dc [Bn * HWn];   // (sqrt-diff, color-diff) fp16
__device__ __align__(16) float   g_gt [Bn * HWn];   // tgt gray fp32 (Sobel: thresholded)
__device__ __align__(16) __half2 g_hrt[Bn * HWn];   // (hsum7_ref, hsum7_tgt) fp16 (ssim only)
__device__ int   g_maxd_i;
__device__ int   g_maxcd_i;
__device__ float g_sum[Bn];
__device__ float g_invd, g_invcd;

static __forceinline__ __device__ unsigned h2u(__half2 h) {
    return *reinterpret_cast<unsigned*>(&h);
}

// ---------------- K0: zero reduction scalars (graph replays!) ------------
__global__ void k0_init() {
    int t = threadIdx.x;
    if (t == 0) g_maxd_i = 0;
    if (t == 1) g_maxcd_i = 0;
    if (t >= 2 && t < 2 + Bn) g_sum[t - 2] = 0.f;
}

// ---------------- K1: one row per block; pointwise + horizontal 7-sums ---
__global__ __launch_bounds__(480) void k1_point(const float* __restrict__ ref,
                                                const float* __restrict__ tgt) {
    const int y = blockIdx.x;
    const int b = blockIdx.y;
    const int t = threadIdx.x;           // 0..479

    __shared__ __align__(16) float srow_r[1928];   // 4 zero pad each side
    __shared__ __align__(16) float srow_t[1928];
    __shared__ float smx[15], smc[15], sms[15];

    if (t < 4) {
        srow_r[t] = 0.f; srow_t[t] = 0.f;
        srow_r[1924 + t] = 0.f; srow_t[1924 + t] = 0.f;
    }

    const size_t rowpx = (size_t)y * Wn + 4 * t;
    const int v = (int)(rowpx >> 2);     // float4 index within plane

    const float4 r0 = ((const float4*)(ref + (size_t)(b * 3 + 0) * HWn))[v];
    const float4 r1 = ((const float4*)(ref + (size_t)(b * 3 + 1) * HWn))[v];
    const float4 r2 = ((const float4*)(ref + (size_t)(b * 3 + 2) * HWn))[v];
    const float4 t0 = ((const float4*)(tgt + (size_t)(b * 3 + 0) * HWn))[v];
    const float4 t1 = ((const float4*)(tgt + (size_t)(b * 3 + 1) * HWn))[v];
    const float4 t2 = ((const float4*)(tgt + (size_t)(b * 3 + 2) * HWn))[v];

    float4 D, C, GR, GT;
    float lmaxd = 0.f, lmaxcd = 0.f, lsum = 0.f;

#define LANE(c)                                                               \
    {                                                                         \
        float d0 = r0.c - t0.c, d1 = r1.c - t1.c, d2 = r2.c - t2.c;           \
        float df = sqrtf(d0 * d0 + d1 * d1 + d2 * d2);                        \
        float cd = (fabsf(d0) + fabsf(d1) + fabsf(d2)) * (1.f / 3.f);         \
        D.c = df; C.c = cd;                                                   \
        GR.c = 0.299f * r0.c + 0.587f * r1.c + 0.114f * r2.c;                 \
        GT.c = 0.299f * t0.c + 0.587f * t1.c + 0.114f * t2.c;                 \
        lmaxd = fmaxf(lmaxd, df); lmaxcd = fmaxf(lmaxcd, cd);                 \
        lsum += df;                                                           \
    }
    LANE(x) LANE(y) LANE(z) LANE(w)
#undef LANE

    // store interleaved (diff, cd) fp16 pairs: one uint4 = 4 pixels
    uint4 dc;
    dc.x = h2u(__floats2half2_rn(D.x, C.x));
    dc.y = h2u(__floats2half2_rn(D.y, C.y));
    dc.z = h2u(__floats2half2_rn(D.z, C.z));
    dc.w = h2u(__floats2half2_rn(D.w, C.w));
    ((uint4*)(g_dc + (size_t)b * HWn))[v] = dc;
    ((float4*)(g_gt + (size_t)b * HWn))[v] = GT;

    // stage gray row for horizontal sums
    *(float4*)&srow_r[4 + 4 * t] = GR;
    *(float4*)&srow_t[4 + 4 * t] = GT;

    // block reduction
    #pragma unroll
    for (int o = 16; o > 0; o >>= 1) {
        lmaxd  = fmaxf(lmaxd,  __shfl_xor_sync(0xffffffffu, lmaxd,  o));
        lmaxcd = fmaxf(lmaxcd, __shfl_xor_sync(0xffffffffu, lmaxcd, o));
        lsum  +=               __shfl_xor_sync(0xffffffffu, lsum,   o);
    }
    const int lane = t & 31, wid = t >> 5;
    if (lane == 0) { smx[wid] = lmaxd; smc[wid] = lmaxcd; sms[wid] = lsum; }
    __syncthreads();
    if (t == 0) {
        float mx = smx[0], mc = smc[0], s = sms[0];
        #pragma unroll
        for (int i = 1; i < 15; i++) {
            mx = fmaxf(mx, smx[i]); mc = fmaxf(mc, smc[i]); s += sms[i];
        }
        atomicMax(&g_maxd_i,  __float_as_int(mx));
        atomicMax(&g_maxcd_i, __float_as_int(mc));
        atomicAdd(&g_sum[b], s);
    }

    // horizontal 7-sums for cols 4t..4t+3 (window +-3, zero padded)
    const float* ar = srow_r + 4 * t;
    const float* at = srow_t + 4 * t;
    float4 A0 = *(const float4*)(ar), A1 = *(const float4*)(ar + 4), A2 = *(const float4*)(ar + 8);
    float4 B0 = *(const float4*)(at), B1 = *(const float4*)(at + 4), B2 = *(const float4*)(at + 8);
    float a[12] = {A0.x,A0.y,A0.z,A0.w, A1.x,A1.y,A1.z,A1.w, A2.x,A2.y,A2.z,A2.w};
    float c[12] = {B0.x,B0.y,B0.z,B0.w, B1.x,B1.y,B1.z,B1.w, B2.x,B2.y,B2.z,B2.w};

    float hr0 = a[1]+a[2]+a[3]+a[4]+a[5]+a[6]+a[7];
    float ht0 = c[1]+c[2]+c[3]+c[4]+c[5]+c[6]+c[7];
    float hr1 = hr0 + a[8] - a[1], ht1 = ht0 + c[8] - c[1];
    float hr2 = hr1 + a[9] - a[2], ht2 = ht1 + c[9] - c[2];
    float hr3 = hr2 + a[10] - a[3], ht3 = ht2 + c[10] - c[3];

    uint4 hq;
    hq.x = h2u(__floats2half2_rn(hr0, ht0));
    hq.y = h2u(__floats2half2_rn(hr1, ht1));
    hq.z = h2u(__floats2half2_rn(hr2, ht2));
    hq.w = h2u(__floats2half2_rn(hr3, ht3));
    ((uint4*)(g_hrt + (size_t)b * HWn))[v] = hq;
}

// ---------------- K2: score + inverse normalizers ------------------------
__global__ void k2_score(float* __restrict__ out) {
    const int t = threadIdx.x;
    const float invd  = 1.f / (__int_as_float(g_maxd_i)  + 1e-12f);
    const float invcd = 1.f / (__int_as_float(g_maxcd_i) + 1e-12f);
    if (t == 0) { g_invd = invd; g_invcd = invcd; }
    if (t < Bn) {
        float m = g_sum[t] * (1.f / (float)HWn) * invd;
        out[t] = fminf(fmaxf(1.f - m, 0.f), 1.f);
    }
}

// ---------------- K3: fused stencils + diagnostic write -------------------
// 32x32 tile, 256 threads (32x8). smem ~18KB, 8 blocks/SM (warp cap).
__global__ __launch_bounds__(256, 8) void k3_stencil(float* __restrict__ diag) {
    const int b  = blockIdx.z;
    const int x0 = blockIdx.x * 32;
    const int y0 = blockIdx.y * 32;

    // region1: sgt (38x41) during stages 1-2, hmax (36x33) during 3-4
    __shared__ __align__(16) float region1[38 * 41];
    float (*sgt)[41]  = reinterpret_cast<float(*)[41]>(region1);
    float (*hmax)[33] = reinterpret_cast<float(*)[33]>(region1);
    __shared__ __align__(16) __half2 shrt[38][36];  // packed (hr,ht); stride 144B
    __shared__ float sedge[36][37];
    __shared__ float sax[32][5];                    // |gx| at cols {0,8,16,24}
    __shared__ float say[4][33];                    // |gy| at rows {0,8,16,24}

    const int tid = threadIdx.y * 32 + threadIdx.x;
    const int x   = threadIdx.x;
    const int gx  = x0 + x;
    const int yb  = threadIdx.y * 4;

    // ---- prefetch interleaved diff/cd for this thread's 4 pixels ----
    const __half2* dcp = g_dc + (size_t)b * HWn;
    __half2 pdc[4];
    #pragma unroll
    for (int r = 0; r < 4; r++) {
        int gy = y0 + yb + r;
        int idx = (gy < Hn) ? gy * Wn + gx : 0;
        pdc[r] = __ldg(dcp + idx);
    }

    const float*   gtb = g_gt  + (size_t)b * HWn;
    const __half2* hqb = g_hrt + (size_t)b * HWn;

    // ---- stage 1a: load hrt tile (38 rows x 32 cols, vertical halo only) ----
    for (int p = tid; p < 38 * 8; p += 256) {
        int j = p >> 3, s = p & 7;
        int y = y0 - 3 + j;
        uint4 V = make_uint4(0u, 0u, 0u, 0u);
        if (y >= 0 && y < Hn)
            V = ((const uint4*)(hqb + (size_t)y * Wn + x0))[s];
        *(uint4*)&shrt[j][4 * s] = V;
    }
    // ---- stage 1b: load gt gray tile (38 x 40 from x0-4, zero-pad) ----
    for (int p = tid; p < 380; p += 256) {
        int j = p / 10, vv = p - j * 10;
        int y = y0 - 3 + j;
        int xg = x0 - 4 + vv * 4;
        float4 C4 = make_float4(0.f, 0.f, 0.f, 0.f);
        if (y >= 0 && y < Hn) {
            const size_t rb = (size_t)y * Wn;
            if (xg >= 0 && xg + 3 < Wn) {
                C4 = *(const float4*)(gtb + rb + xg);
            } else {
                if (xg + 0 >= 0 && xg + 0 < Wn) C4.x = gtb[rb + xg];
                if (xg + 1 >= 0 && xg + 1 < Wn) C4.y = gtb[rb + xg + 1];
                if (xg + 2 >= 0 && xg + 2 < Wn) C4.z = gtb[rb + xg + 2];
                if (xg + 3 >= 0 && xg + 3 < Wn) C4.w = gtb[rb + xg + 3];
            }
        }
        const int c0 = vv * 4;
        sgt[j][c0] = C4.x; sgt[j][c0 + 1] = C4.y; sgt[j][c0 + 2] = C4.z; sgt[j][c0 + 3] = C4.w;
    }
    __syncthreads();

    // ---- stage 2: Sobel + edge map over halo-2 region, groups of 6 ----
    for (int p = tid; p < 36 * 6; p += 256) {
        int j = p / 6, g = p - j * 6;
        int i0 = g * 6;
        float r0[8], r1[8], r2[8];
        #pragma unroll
        for (int k = 0; k < 8; k++) {
            r0[k] = sgt[j][i0 + 1 + k];
            r1[k] = sgt[j + 1][i0 + 1 + k];
            r2[k] = sgt[j + 2][i0 + 1 + k];
        }
        #pragma unroll
        for (int q = 0; q < 6; q++) {
            float gxv = (r0[q+2] - r0[q]) + 2.f * (r1[q+2] - r1[q]) + (r2[q+2] - r2[q]);
            float gyv = (r2[q] - r0[q]) + 2.f * (r2[q+1] - r0[q+1]) + (r2[q+2] - r0[q+2]);
            int i  = i0 + q;
            int ye = y0 - 2 + j, xe = x0 - 2 + i;
            bool in = (ye >= 0) & (ye < Hn) & (xe >= 0) & (xe < Wn);
            float e = (in && (sqrtf(gxv * gxv + gyv * gyv) > 0.15f)) ? 1.f : 0.f;
            sedge[j][i] = e;
            int yl = j - 2, xl = i - 2;
            if (((xl & 7) == 0) & (xl >= 0) & (xl < 32) & (yl >= 0) & (yl < 32))
                sax[yl][xl >> 3] = fabsf(gxv);
            if (((yl & 7) == 0) & (yl >= 0) & (yl < 32) & (xl >= 0) & (xl < 32))
                say[yl >> 3][xl] = fabsf(gyv);
        }
    }
    __syncthreads();   // sgt dead; region1 becomes hmax

    // ---- stage 3: horizontal 5-max of edges, groups of 8 ----
    for (int p = tid; p < 36 * 4; p += 256) {
        int j = p >> 2, g = p & 3;
        int xg = g * 8;
        float v[12];
        #pragma unroll
        for (int k = 0; k < 12; k++) v[k] = sedge[j][xg + k];
        float t2[10];
        #pragma unroll
        for (int k = 0; k < 10; k++) t2[k] = fmaxf(v[k], v[k + 1]);
        #pragma unroll
        for (int q = 0; q < 8; q++)
            hmax[j][xg + q] = fmaxf(fmaxf(t2[q], t2[q + 2]), v[q + 4]);
    }
    __syncthreads();

    // ---- stage 4: per-pixel outputs, 4 consecutive rows per thread ----
    const float invd  = g_invd;
    const float invcd = g_invcd;
    float* o_an = diag + ((size_t)b * 5 + 0) * HWn;
    float* o_cm = diag + ((size_t)b * 5 + 1) * HWn;
    float* o_ss = diag + ((size_t)b * 5 + 2) * HWn;
    float* o_bl = diag + ((size_t)b * 5 + 3) * HWn;
    float* o_ri = diag + ((size_t)b * 5 + 4) * HWn;

    float2 vrt[10];
    #pragma unroll
    for (int k = 0; k < 10; k++) vrt[k] = __half22float2(shrt[yb + k][x]);
    float mur[4], mut[4];
    {
        float sr = vrt[0].x + vrt[1].x + vrt[2].x + vrt[3].x + vrt[4].x + vrt[5].x + vrt[6].x;
        float st = vrt[0].y + vrt[1].y + vrt[2].y + vrt[3].y + vrt[4].y + vrt[5].y + vrt[6].y;
        mur[0] = sr; mut[0] = st;
        sr += vrt[7].x - vrt[0].x; st += vrt[7].y - vrt[0].y; mur[1] = sr; mut[1] = st;
        sr += vrt[8].x - vrt[1].x; st += vrt[8].y - vrt[1].y; mur[2] = sr; mut[2] = st;
        sr += vrt[9].x - vrt[2].x; st += vrt[9].y - vrt[2].y; mur[3] = sr; mut[3] = st;
    }

    float hm[8];
    #pragma unroll
    for (int k = 0; k < 8; k++) hm[k] = hmax[yb + k][x];
    float dil[4];
    {
        float m34 = fmaxf(hm[3], hm[4]);
        float m234 = fmaxf(hm[2], m34);
        float m345 = fmaxf(m34, hm[5]);
        dil[0] = fmaxf(fmaxf(hm[0], hm[1]), m234);
        dil[1] = fmaxf(hm[1], fmaxf(m234, hm[5]));
        dil[2] = fmaxf(hm[2], fmaxf(m345, hm[6]));
        dil[3] = fmaxf(fmaxf(m345, hm[6]), hm[7]);
    }

    float ev[4];
    #pragma unroll
    for (int r = 0; r < 4; r++) ev[r] = sedge[yb + r + 2][x + 2];

    const bool colblk = ((gx & 7) == 0);
    float axv[4];
    #pragma unroll
    for (int r = 0; r < 4; r++) axv[r] = colblk ? sax[yb + r][x >> 3] : 0.f;

    #pragma unroll
    for (int r = 0; r < 4; r++) {
        const int y  = yb + r;
        const int gy = y0 + y;
        if (gy >= Hn) continue;

        float mu_r = mur[r] * (1.f / 49.f), mu_t = mut[r] * (1.f / 49.f);
        float ssim = (2.f * mu_r * mu_t + 1e-4f) / (mu_r * mu_r + mu_t * mu_t + 1e-4f);

        float blk = axv[r];
        if ((y & 7) == 0) blk = fmaxf(blk, say[y >> 3][x]);
        blk = (blk > 0.05f) ? 1.f : 0.f;

        const int idx = gy * Wn + gx;
        float2 dc  = __half22float2(pdc[r]);
        float an   = dc.x * invd;
        float cm   = dc.y * invcd;
        float ring = fmaxf(dil[r] - ev[r], 0.f) * an;

        o_an[idx] = an;
        o_cm[idx] = cm;
        o_ss[idx] = ssim;
        o_bl[idx] = blk;
        o_ri[idx] = ring;
    }
}

// ---------------- launch ---------------------------------------------------
extern "C" void kernel_launch(void* const* d_in, const int* in_sizes, int n_in,
                              void* d_out, int out_size) {
    const float* ref = (const float*)d_in[0];
    const float* tgt = (const float*)d_in[1];
    float* out = (float*)d_out;

    k0_init<<<1, 32>>>();

    dim3 g1(Hn, Bn);
    k1_point<<<g1, 480>>>(ref, tgt);

    k2_score<<<1, 32>>>(out);

    dim3 g3((Wn + 31) / 32, (Hn + 31) / 32, Bn);
    dim3 b3(32, 8);
    k3_stencil<<<g3, b3>>>(out + Bn);
}